// round 1
// baseline (speedup 1.0000x reference)
#include <cuda_runtime.h>
#include <float.h>
#include <math.h>

// Problem constants (from reference)
#define DIMD   4096
#define NEXP   256
#define NGRP   8
#define GSZ    32      // experts per group
#define TOPKG  4
#define TOPK   8
#define MAXT   16384

// Scratch for logits [T, NEXP] (device global: allocation-free per harness rules)
__device__ float g_logits[MAXT * NEXP];

// ---------------------------------------------------------------------------
// Kernel 1: fp32 SGEMM  L[t,e] = sum_d X[t,d] * W[e,d]
// BM=BN=128, BK=16, 256 threads, 8x8 accum per thread.
// ---------------------------------------------------------------------------
__global__ void __launch_bounds__(256, 2)
gate_gemm_kernel(const float* __restrict__ X, const float* __restrict__ W, int T)
{
    __shared__ float As[16][128];
    __shared__ float Bs[16][128];

    const int tid = threadIdx.x;
    const int m0  = blockIdx.y * 128;
    const int n0  = blockIdx.x * 128;
    const int tx  = tid & 15;    // 0..15 -> N
    const int ty  = tid >> 4;    // 0..15 -> M

    float acc[8][8];
#pragma unroll
    for (int i = 0; i < 8; i++)
#pragma unroll
        for (int j = 0; j < 8; j++) acc[i][j] = 0.f;

    for (int k0 = 0; k0 < DIMD; k0 += 16) {
        // Load 128x16 tiles of X and W, store transposed into smem.
        // 512 float4 per tile / 256 threads = 2 each.
#pragma unroll
        for (int u = 0; u < 2; u++) {
            int idx = tid + u * 256;
            int row = idx >> 2;   // 0..127
            int c4  = idx & 3;    // which float4 within the 16-wide K slab
            float4 a = *(const float4*)(X + (size_t)(m0 + row) * DIMD + k0 + c4 * 4);
            As[c4 * 4 + 0][row] = a.x;
            As[c4 * 4 + 1][row] = a.y;
            As[c4 * 4 + 2][row] = a.z;
            As[c4 * 4 + 3][row] = a.w;
            float4 b = *(const float4*)(W + (size_t)(n0 + row) * DIMD + k0 + c4 * 4);
            Bs[c4 * 4 + 0][row] = b.x;
            Bs[c4 * 4 + 1][row] = b.y;
            Bs[c4 * 4 + 2][row] = b.z;
            Bs[c4 * 4 + 3][row] = b.w;
        }
        __syncthreads();

#pragma unroll
        for (int k = 0; k < 16; k++) {
            float a[8], b[8];
#pragma unroll
            for (int i = 0; i < 8; i++) a[i] = As[k][ty * 8 + i];
#pragma unroll
            for (int j = 0; j < 8; j++) b[j] = Bs[k][tx * 8 + j];
#pragma unroll
            for (int i = 0; i < 8; i++)
#pragma unroll
                for (int j = 0; j < 8; j++) acc[i][j] = fmaf(a[i], b[j], acc[i][j]);
        }
        __syncthreads();
    }

#pragma unroll
    for (int i = 0; i < 8; i++) {
        float* out = g_logits + (size_t)(m0 + ty * 8 + i) * NEXP + n0 + tx * 8;
#pragma unroll
        for (int j = 0; j < 8; j += 4) {
            float4 v = make_float4(acc[i][j], acc[i][j + 1], acc[i][j + 2], acc[i][j + 3]);
            *(float4*)(out + j) = v;
        }
    }
}

// ---------------------------------------------------------------------------
// Kernel 2: per-token softmax + group-limited top-k routing. One warp/token.
// Lane layout: lane holds experts e = j*32 + lane for j in 0..7, so register
// slot j is exactly group j.
// ---------------------------------------------------------------------------
__global__ void gate_route_kernel(float* __restrict__ wout,
                                  float* __restrict__ iout,
                                  int T, int two_out)
{
    const int warp = (blockIdx.x * blockDim.x + threadIdx.x) >> 5;
    const int lane = threadIdx.x & 31;
    if (warp >= T) return;

    const float* l = g_logits + (size_t)warp * NEXP;

    float v[8];
#pragma unroll
    for (int j = 0; j < 8; j++) v[j] = l[j * 32 + lane];

    // ---- softmax (fp32) ----
    float m = v[0];
#pragma unroll
    for (int j = 1; j < 8; j++) m = fmaxf(m, v[j]);
#pragma unroll
    for (int o = 16; o; o >>= 1) m = fmaxf(m, __shfl_xor_sync(0xffffffffu, m, o));

    float e[8], s = 0.f;
#pragma unroll
    for (int j = 0; j < 8; j++) { e[j] = expf(v[j] - m); s += e[j]; }
#pragma unroll
    for (int o = 16; o; o >>= 1) s += __shfl_xor_sync(0xffffffffu, s, o);
    const float inv = 1.f / s;   // score[j,lane] = e[j]*inv; ordering of e == ordering of scores

    // ---- group maxima (8 groups, group j == register slot j) ----
    float gm[8];
#pragma unroll
    for (int j = 0; j < 8; j++) {
        float g = v[j];
#pragma unroll
        for (int o = 16; o; o >>= 1) g = fmaxf(g, __shfl_xor_sync(0xffffffffu, g, o));
        gm[j] = g;   // identical on all lanes
    }

    // ---- top-4 groups (tie -> lower group index, matching jax top_k) ----
    unsigned keep = 0;
#pragma unroll
    for (int r = 0; r < 4; r++) {
        int best = -1; float bv = -FLT_MAX;
#pragma unroll
        for (int g = 0; g < 8; g++) {
            if (keep & (1u << g)) continue;
            if (gm[g] > bv) { bv = gm[g]; best = g; }
        }
        keep |= 1u << best;
    }

    // ---- masked candidates (softmax-monotonic: compare on e[]) ----
    float mv[8];
#pragma unroll
    for (int j = 0; j < 8; j++) mv[j] = ((keep >> j) & 1u) ? e[j] : -FLT_MAX;

    // ---- iterative top-8 with lexicographic (value desc, index asc) order ----
#pragma unroll
    for (int r = 0; r < 8; r++) {
        float bv = -FLT_MAX; int bi = NEXP;
#pragma unroll
        for (int j = 0; j < 8; j++) {
            int idx = j * 32 + lane;
            if (mv[j] > bv || (mv[j] == bv && idx < bi)) { bv = mv[j]; bi = idx; }
        }
#pragma unroll
        for (int o = 16; o; o >>= 1) {
            float ov = __shfl_xor_sync(0xffffffffu, bv, o);
            int   oi = __shfl_xor_sync(0xffffffffu, bi, o);
            if (ov > bv || (ov == bv && oi < bi)) { bv = ov; bi = oi; }
        }
        // record result r
        if (lane == r) {
            wout[(size_t)warp * TOPK + r] = bv * inv;   // ROUTE_SCALE = 1.0
            if (two_out) iout[(size_t)warp * TOPK + r] = (float)bi;
        }
        // mark winner as taken (owning lane clears its slot)
        int jj = bi >> 5, ll = bi & 31;
#pragma unroll
        for (int j = 0; j < 8; j++)
            if (j == jj && lane == ll) mv[j] = -FLT_MAX;
    }
}

// ---------------------------------------------------------------------------
extern "C" void kernel_launch(void* const* d_in, const int* in_sizes, int n_in,
                              void* d_out, int out_size)
{
    const float* X = (const float*)d_in[0];
    const float* W = (const float*)d_in[1];
    const int T = in_sizes[0] / DIMD;      // 16384

    dim3 gblock(256);
    dim3 ggrid(NEXP / 128, T / 128);
    gate_gemm_kernel<<<ggrid, gblock>>>(X, W, T);

    // Output layout: weights [T,8] first; if room, indices (as float) after.
    float* wout = (float*)d_out;
    int two_out = (out_size >= 2 * T * TOPK) ? 1 : 0;
    float* iout = wout + (size_t)T * TOPK;

    int nwarps = T;
    int threads = 256;
    int blocks = (nwarps * 32 + threads - 1) / threads;
    gate_route_kernel<<<blocks, threads>>>(wout, iout, T, two_out);
}